// round 6
// baseline (speedup 1.0000x reference)
#include <cuda_runtime.h>
#include <cstdint>

#define N_NODES   50000
#define IN_FEAT   128
#define OUT_FEAT  128
#define NB        16
#define SI        8
#define SO        8
#define W_PER_REL (NB * SI * SO)   // 1024
#define E_MAX     500000
#define MAXR      200
#define NBLK2     232               // one wave of fat sort blocks
#define SORT_TPB  256
#define EPW       8                 // edges per warp in edge kernel

// Scratch (static device globals — allocation-free per harness rules)
__device__ int4 g_edges[E_MAX];            // (src, dst, etype, norm_bits), etype-sorted
__device__ int  g_bh[MAXR * NBLK2];        // per-(rel, block) counts -> base offsets

// ---------------------------------------------------------------------------
__device__ __forceinline__ void red_add_v4(float* addr, float4 v) {
    asm volatile("red.global.add.v4.f32 [%0], {%1, %2, %3, %4};"
                 :: "l"(addr), "f"(v.x), "f"(v.y), "f"(v.z), "f"(v.w)
                 : "memory");
}

// ---------------------------------------------------------------------------
// Sort pass 1: per-block histogram over contiguous edge chunk (grid = NBLK2)
// ---------------------------------------------------------------------------
__global__ __launch_bounds__(SORT_TPB) void k_hist(const int* __restrict__ et,
                                                   int n, int chunk) {
    __shared__ int sh[MAXR];
    int tid = threadIdx.x, bid = blockIdx.x;
    if (tid < MAXR) sh[tid] = 0;
    __syncthreads();
    int lo = bid * chunk;
    int hi = lo + chunk; if (hi > n) hi = n;
    for (int e = lo + tid; e < hi; e += SORT_TPB)
        atomicAdd(&sh[et[e]], 1);
    __syncthreads();
    if (tid < MAXR) g_bh[tid * NBLK2 + bid] = sh[tid];
}

// ---------------------------------------------------------------------------
// Sort pass 2: ONE block turns g_bh counts into exclusive base offsets.
// ---------------------------------------------------------------------------
__global__ __launch_bounds__(256) void k_scan() {
    __shared__ int rel_total[256];
    __shared__ int rel_base[256];
    __shared__ int sc[256];
    int t = threadIdx.x, warp = t >> 5, lane = t & 31;

    // phase 1: per-relation totals (warp-parallel row sums)
    for (int r = warp; r < MAXR; r += 8) {
        int s = 0;
        for (int j = lane; j < NBLK2; j += 32) s += g_bh[r * NBLK2 + j];
#pragma unroll
        for (int o = 16; o; o >>= 1) s += __shfl_xor_sync(~0u, s, o);
        if (lane == 0) rel_total[r] = s;
    }
    __syncthreads();

    // phase 2: exclusive scan of relation totals (Hillis-Steele over 256)
    int v = (t < MAXR) ? rel_total[t] : 0;
    sc[t] = v;
    __syncthreads();
    for (int off = 1; off < 256; off <<= 1) {
        int y = (t >= off) ? sc[t - off] : 0;
        __syncthreads();
        sc[t] += y;
        __syncthreads();
    }
    if (t < MAXR) rel_base[t] = sc[t] - v;
    __syncthreads();

    // phase 3: per-relation exclusive scans over blocks, carried shfl scans
    for (int r = warp; r < MAXR; r += 8) {
        int carry = rel_base[r];
        for (int base = 0; base < NBLK2; base += 32) {
            int j = base + lane;
            int val = (j < NBLK2) ? g_bh[r * NBLK2 + j] : 0;
            int inc = val;
#pragma unroll
            for (int o = 1; o < 32; o <<= 1) {
                int y = __shfl_up_sync(~0u, inc, o);
                if (lane >= o) inc += y;
            }
            if (j < NBLK2) g_bh[r * NBLK2 + j] = carry + inc - val;
            carry += __shfl_sync(~0u, inc, 31);
        }
    }
}

// ---------------------------------------------------------------------------
// Sort pass 3: scatter with shared cursors (no global atomics)
// ---------------------------------------------------------------------------
__global__ __launch_bounds__(SORT_TPB) void k_scatter(const int* __restrict__ src,
                                                      const int* __restrict__ dst,
                                                      const int* __restrict__ et,
                                                      const float* __restrict__ norm,
                                                      int n, int chunk) {
    __shared__ int cur[MAXR];
    int tid = threadIdx.x, bid = blockIdx.x;
    if (tid < MAXR) cur[tid] = g_bh[tid * NBLK2 + bid];
    __syncthreads();
    int lo = bid * chunk;
    int hi = lo + chunk; if (hi > n) hi = n;
    for (int e = lo + tid; e < hi; e += SORT_TPB) {
        int t = et[e];
        int d = dst[e];
        int s = src[e];
        float nv = __ldg(norm + d);
        int pos = atomicAdd(&cur[t], 1);
        int4 ed;
        ed.x = s;
        ed.y = d;
        ed.z = t;
        ed.w = __float_as_int(nv);
        g_edges[pos] = ed;
    }
}

// ---------------------------------------------------------------------------
// Kernel A: d_out = h @ loop_weight  (register-tiled, 64 rows x 128 cols/block)
// ---------------------------------------------------------------------------
#define GM_ROWS 64
__global__ __launch_bounds__(256) void loop_gemm_kernel(
        const float* __restrict__ h,
        const float* __restrict__ lw,
        float* __restrict__ out) {
    __shared__ float4 xs[GM_ROWS][32];
    int r0 = blockIdx.x * GM_ROWS;
    int tid = threadIdx.x;

    const float4* h4 = reinterpret_cast<const float4*>(h);
    for (int idx = tid; idx < GM_ROWS * 32; idx += 256) {
        int r = idx >> 5, c = idx & 31;
        int gr = r0 + r;
        xs[r][c] = (gr < N_NODES) ? __ldg(&h4[(size_t)gr * 32 + c])
                                  : make_float4(0.f, 0.f, 0.f, 0.f);
    }
    __syncthreads();

    int cx = tid & 31;
    int rg = (tid >> 5) * 8;

    float4 acc[8];
#pragma unroll
    for (int r = 0; r < 8; r++) acc[r] = make_float4(0.f, 0.f, 0.f, 0.f);

    const float4* lw4 = reinterpret_cast<const float4*>(lw);
    const float* xrow = reinterpret_cast<const float*>(&xs[rg][0]);

#pragma unroll 4
    for (int k = 0; k < IN_FEAT; k++) {
        float4 w = __ldg(&lw4[(size_t)k * 32 + cx]);
#pragma unroll
        for (int r = 0; r < 8; r++) {
            float x = xrow[r * IN_FEAT + k];
            acc[r].x = fmaf(x, w.x, acc[r].x);
            acc[r].y = fmaf(x, w.y, acc[r].y);
            acc[r].z = fmaf(x, w.z, acc[r].z);
            acc[r].w = fmaf(x, w.w, acc[r].w);
        }
    }

    float4* out4 = reinterpret_cast<float4*>(out);
#pragma unroll
    for (int r = 0; r < 8; r++) {
        int gr = r0 + rg + r;
        if (gr < N_NODES) out4[(size_t)gr * 32 + cx] = acc[r];
    }
}

// ---------------------------------------------------------------------------
// Kernel B: each warp processes EPW consecutive etype-sorted edges.
// ---------------------------------------------------------------------------
struct EdgeCtx {
    int b, o0, par, xoff;
    int t_cur;
    float4 w[SI];
};

__device__ __forceinline__ void process_edge(
        const float* __restrict__ h,
        const float* __restrict__ weight,
        float* __restrict__ out,
        EdgeCtx& c, int4 ed, int lane) {
    int s = ed.x, d = ed.y, t = ed.z;
    float nrm = __int_as_float(ed.w);

    if (t != c.t_cur) {                       // warp-uniform branch
        c.t_cur = t;
        const float* wb = weight + (size_t)t * W_PER_REL + c.b * (SI * SO) + c.o0;
#pragma unroll
        for (int j = 0; j < SI; j++) {
            int row = (j + c.par * 4) & 7;    // permute for lane parity
            c.w[j] = __ldg(reinterpret_cast<const float4*>(wb + row * SO));
        }
    }

    // coalesced load of my half, shuffle for partner half
    float4 xm = __ldg(reinterpret_cast<const float4*>(h + (size_t)s * IN_FEAT + c.xoff));
    float4 xo;
    xo.x = __shfl_xor_sync(~0u, xm.x, 1);
    xo.y = __shfl_xor_sync(~0u, xm.y, 1);
    xo.z = __shfl_xor_sync(~0u, xm.z, 1);
    xo.w = __shfl_xor_sync(~0u, xm.w, 1);

    float x[8] = {xm.x, xm.y, xm.z, xm.w, xo.x, xo.y, xo.z, xo.w};

    float4 acc = make_float4(0.f, 0.f, 0.f, 0.f);
#pragma unroll
    for (int j = 0; j < SI; j++) {
        acc.x = fmaf(x[j], c.w[j].x, acc.x);
        acc.y = fmaf(x[j], c.w[j].y, acc.y);
        acc.z = fmaf(x[j], c.w[j].z, acc.z);
        acc.w = fmaf(x[j], c.w[j].w, acc.w);
    }

    acc.x *= nrm; acc.y *= nrm; acc.z *= nrm; acc.w *= nrm;
    red_add_v4(out + (size_t)d * OUT_FEAT + lane * 4, acc);
}

__global__ __launch_bounds__(256) void edge_kernel(
        const float* __restrict__ h,
        const float* __restrict__ weight,
        float* __restrict__ out,
        int nedges) {
    int gw   = (blockIdx.x * blockDim.x + threadIdx.x) >> 5;
    int lane = threadIdx.x & 31;
    int e0 = gw * EPW;
    if (e0 >= nedges) return;            // warp-uniform

    EdgeCtx c;
    c.b = lane >> 1;
    c.par = lane & 1;
    c.o0 = c.par * 4;
    c.xoff = c.b * SI + c.par * 4;
    c.t_cur = -1;

    if (e0 + EPW <= nedges) {
        int4 eds[EPW];
#pragma unroll
        for (int k = 0; k < EPW; k++) eds[k] = g_edges[e0 + k];  // MLP=8
#pragma unroll
        for (int k = 0; k < EPW; k++) process_edge(h, weight, out, c, eds[k], lane);
    } else {
        for (int e = e0; e < nedges; e++) {
            int4 ed = g_edges[e];
            process_edge(h, weight, out, c, ed, lane);
        }
    }
}

// ---------------------------------------------------------------------------
// Kernel C: in-place ReLU (float4 vectorized)
// ---------------------------------------------------------------------------
__global__ void relu_kernel(float4* __restrict__ out, int n4) {
    int i = blockIdx.x * blockDim.x + threadIdx.x;
    if (i >= n4) return;
    float4 v = out[i];
    v.x = fmaxf(v.x, 0.f);
    v.y = fmaxf(v.y, 0.f);
    v.z = fmaxf(v.z, 0.f);
    v.w = fmaxf(v.w, 0.f);
    out[i] = v;
}

// ---------------------------------------------------------------------------
// Launch: 3-kernel sort -> GEMM init -> edge scatter -> ReLU
// Inputs (metadata order): h, norm, weight, loop_weight, src, dst, etype
// ---------------------------------------------------------------------------
extern "C" void kernel_launch(void* const* d_in, const int* in_sizes, int n_in,
                              void* d_out, int out_size) {
    const float* h      = (const float*)d_in[0];
    const float* norm   = (const float*)d_in[1];
    const float* weight = (const float*)d_in[2];
    const float* lw     = (const float*)d_in[3];
    const int*   src    = (const int*)d_in[4];
    const int*   dst    = (const int*)d_in[5];
    const int*   etype  = (const int*)d_in[6];
    float* out = (float*)d_out;

    int nedges = in_sizes[4];
    if (nedges > E_MAX) nedges = E_MAX;
    int chunk = (nedges + NBLK2 - 1) / NBLK2;

    // ---- contention-free counting sort by etype (3 kernels) ----
    k_hist<<<NBLK2, SORT_TPB>>>(etype, nedges, chunk);
    k_scan<<<1, 256>>>();
    k_scatter<<<NBLK2, SORT_TPB>>>(src, dst, etype, norm, nedges, chunk);

    // ---- self-loop GEMM (initializes d_out) ----
    loop_gemm_kernel<<<(N_NODES + GM_ROWS - 1) / GM_ROWS, 256>>>(h, lw, out);

    // ---- per-edge messages (W cached in registers; coalesced x loads) ----
    {
        int nwarps = (nedges + EPW - 1) / EPW;
        int blocks = (nwarps + 7) / 8;       // 8 warps / block
        edge_kernel<<<blocks, 256>>>(h, weight, out, nedges);
    }

    // ---- ReLU ----
    {
        int n4 = N_NODES * OUT_FEAT / 4;
        relu_kernel<<<(n4 + 255) / 256, 256>>>((float4*)out, n4);
    }
}

// round 7
// speedup vs baseline: 1.0481x; 1.0481x over previous
#include <cuda_runtime.h>
#include <cstdint>

#define N_NODES   50000
#define IN_FEAT   128
#define OUT_FEAT  128
#define NB        16
#define SI        8
#define SO        8
#define W_PER_REL (NB * SI * SO)   // 1024
#define E_MAX     500000
#define MAXR      200
#define NBLK2     232               // one wave of fat sort blocks
#define SORT_TPB  256
#define EPW       8                 // edges per warp in edge kernel

// Scratch (static device globals — allocation-free per harness rules)
__device__ int4 g_edges[E_MAX];            // (src, dst, etype, norm_bits), etype-sorted
__device__ int  g_bh[MAXR * NBLK2];        // per-(rel, block) counts -> base offsets

// ---------------------------------------------------------------------------
__device__ __forceinline__ void red_add_v4(float* addr, float4 v) {
    asm volatile("red.global.add.v4.f32 [%0], {%1, %2, %3, %4};"
                 :: "l"(addr), "f"(v.x), "f"(v.y), "f"(v.z), "f"(v.w)
                 : "memory");
}

// ---------------------------------------------------------------------------
// Sort pass 1: per-block histogram over contiguous edge chunk (grid = NBLK2)
// ---------------------------------------------------------------------------
__global__ __launch_bounds__(SORT_TPB) void k_hist(const int* __restrict__ et,
                                                   int n, int chunk) {
    __shared__ int sh[MAXR];
    int tid = threadIdx.x, bid = blockIdx.x;
    if (tid < MAXR) sh[tid] = 0;
    __syncthreads();
    int lo = bid * chunk;
    int hi = lo + chunk; if (hi > n) hi = n;
    for (int e = lo + tid; e < hi; e += SORT_TPB)
        atomicAdd(&sh[et[e]], 1);
    __syncthreads();
    if (tid < MAXR) g_bh[tid * NBLK2 + bid] = sh[tid];
}

// ---------------------------------------------------------------------------
// Sort pass 2: ONE block turns g_bh counts into exclusive base offsets.
// ---------------------------------------------------------------------------
__global__ __launch_bounds__(256) void k_scan() {
    __shared__ int rel_total[256];
    __shared__ int rel_base[256];
    __shared__ int sc[256];
    int t = threadIdx.x, warp = t >> 5, lane = t & 31;

    // phase 1: per-relation totals (warp-parallel row sums)
    for (int r = warp; r < MAXR; r += 8) {
        int s = 0;
        for (int j = lane; j < NBLK2; j += 32) s += g_bh[r * NBLK2 + j];
#pragma unroll
        for (int o = 16; o; o >>= 1) s += __shfl_xor_sync(~0u, s, o);
        if (lane == 0) rel_total[r] = s;
    }
    __syncthreads();

    // phase 2: exclusive scan of relation totals (Hillis-Steele over 256)
    int v = (t < MAXR) ? rel_total[t] : 0;
    sc[t] = v;
    __syncthreads();
    for (int off = 1; off < 256; off <<= 1) {
        int y = (t >= off) ? sc[t - off] : 0;
        __syncthreads();
        sc[t] += y;
        __syncthreads();
    }
    if (t < MAXR) rel_base[t] = sc[t] - v;
    __syncthreads();

    // phase 3: per-relation exclusive scans over blocks, carried shfl scans
    for (int r = warp; r < MAXR; r += 8) {
        int carry = rel_base[r];
        for (int base = 0; base < NBLK2; base += 32) {
            int j = base + lane;
            int val = (j < NBLK2) ? g_bh[r * NBLK2 + j] : 0;
            int inc = val;
#pragma unroll
            for (int o = 1; o < 32; o <<= 1) {
                int y = __shfl_up_sync(~0u, inc, o);
                if (lane >= o) inc += y;
            }
            if (j < NBLK2) g_bh[r * NBLK2 + j] = carry + inc - val;
            carry += __shfl_sync(~0u, inc, 31);
        }
    }
}

// ---------------------------------------------------------------------------
// Sort pass 3: scatter with shared cursors (no global atomics)
// ---------------------------------------------------------------------------
__global__ __launch_bounds__(SORT_TPB) void k_scatter(const int* __restrict__ src,
                                                      const int* __restrict__ dst,
                                                      const int* __restrict__ et,
                                                      const float* __restrict__ norm,
                                                      int n, int chunk) {
    __shared__ int cur[MAXR];
    int tid = threadIdx.x, bid = blockIdx.x;
    if (tid < MAXR) cur[tid] = g_bh[tid * NBLK2 + bid];
    __syncthreads();
    int lo = bid * chunk;
    int hi = lo + chunk; if (hi > n) hi = n;
    for (int e = lo + tid; e < hi; e += SORT_TPB) {
        int t = et[e];
        int d = dst[e];
        int s = src[e];
        float nv = __ldg(norm + d);
        int pos = atomicAdd(&cur[t], 1);
        int4 ed;
        ed.x = s;
        ed.y = d;
        ed.z = t;
        ed.w = __float_as_int(nv);
        g_edges[pos] = ed;
    }
}

// ---------------------------------------------------------------------------
// Kernel A: d_out = h @ loop_weight  (register-tiled, 64 rows x 128 cols/block)
// k-loop vectorized by 4: per chunk 4x LDG.128 (w) + 8x broadcast LDS.128 (x)
// + 128 FMA  -> FMA-slot fraction ~91%.
// ---------------------------------------------------------------------------
#define GM_ROWS 64
__global__ __launch_bounds__(256) void loop_gemm_kernel(
        const float* __restrict__ h,
        const float* __restrict__ lw,
        float* __restrict__ out) {
    __shared__ float4 xs[GM_ROWS][32];   // row r: k 0..127 as 32 float4
    int r0 = blockIdx.x * GM_ROWS;
    int tid = threadIdx.x;

    const float4* h4 = reinterpret_cast<const float4*>(h);
    for (int idx = tid; idx < GM_ROWS * 32; idx += 256) {
        int r = idx >> 5, c = idx & 31;
        int gr = r0 + r;
        xs[r][c] = (gr < N_NODES) ? __ldg(&h4[(size_t)gr * 32 + c])
                                  : make_float4(0.f, 0.f, 0.f, 0.f);
    }
    __syncthreads();

    int cx = tid & 31;          // float4 col index (cols 4cx..4cx+3)
    int rg = (tid >> 5) * 8;    // row base within tile

    float4 acc[8];
#pragma unroll
    for (int r = 0; r < 8; r++) acc[r] = make_float4(0.f, 0.f, 0.f, 0.f);

    const float4* lw4 = reinterpret_cast<const float4*>(lw);

    for (int k4 = 0; k4 < 32; k4++) {        // 4 k-values per iteration
        float4 w0 = __ldg(&lw4[(size_t)(k4 * 4 + 0) * 32 + cx]);
        float4 w1 = __ldg(&lw4[(size_t)(k4 * 4 + 1) * 32 + cx]);
        float4 w2 = __ldg(&lw4[(size_t)(k4 * 4 + 2) * 32 + cx]);
        float4 w3 = __ldg(&lw4[(size_t)(k4 * 4 + 3) * 32 + cx]);
#pragma unroll
        for (int r = 0; r < 8; r++) {
            float4 xv = xs[rg + r][k4];      // warp-broadcast LDS.128
            acc[r].x = fmaf(xv.x, w0.x, acc[r].x);
            acc[r].y = fmaf(xv.x, w0.y, acc[r].y);
            acc[r].z = fmaf(xv.x, w0.z, acc[r].z);
            acc[r].w = fmaf(xv.x, w0.w, acc[r].w);
            acc[r].x = fmaf(xv.y, w1.x, acc[r].x);
            acc[r].y = fmaf(xv.y, w1.y, acc[r].y);
            acc[r].z = fmaf(xv.y, w1.z, acc[r].z);
            acc[r].w = fmaf(xv.y, w1.w, acc[r].w);
            acc[r].x = fmaf(xv.z, w2.x, acc[r].x);
            acc[r].y = fmaf(xv.z, w2.y, acc[r].y);
            acc[r].z = fmaf(xv.z, w2.z, acc[r].z);
            acc[r].w = fmaf(xv.z, w2.w, acc[r].w);
            acc[r].x = fmaf(xv.w, w3.x, acc[r].x);
            acc[r].y = fmaf(xv.w, w3.y, acc[r].y);
            acc[r].z = fmaf(xv.w, w3.z, acc[r].z);
            acc[r].w = fmaf(xv.w, w3.w, acc[r].w);
        }
    }

    float4* out4 = reinterpret_cast<float4*>(out);
#pragma unroll
    for (int r = 0; r < 8; r++) {
        int gr = r0 + rg + r;
        if (gr < N_NODES) out4[(size_t)gr * 32 + cx] = acc[r];
    }
}

// ---------------------------------------------------------------------------
// Kernel B (R3 proven form): each warp processes EPW consecutive etype-sorted
// edges; W cached in registers across edges; records prefetched (MLP=8).
//   lane l: basis block b = l>>1, output offset o0 = (l&1)*4
// ---------------------------------------------------------------------------
struct EdgeCtx {
    int b, o0;
    int t_cur;
    float4 w[SI];
};

__device__ __forceinline__ void process_edge(
        const float* __restrict__ h,
        const float* __restrict__ weight,
        float* __restrict__ out,
        EdgeCtx& c, int4 ed, int lane) {
    int s = ed.x, d = ed.y, t = ed.z;
    float nrm = __int_as_float(ed.w);

    if (t != c.t_cur) {                       // warp-uniform branch
        c.t_cur = t;
        const float* wb = weight + (size_t)t * W_PER_REL + c.b * (SI * SO) + c.o0;
#pragma unroll
        for (int i = 0; i < SI; i++)
            c.w[i] = __ldg(reinterpret_cast<const float4*>(wb + i * SO));
    }

    const float4* xp = reinterpret_cast<const float4*>(h + (size_t)s * IN_FEAT + c.b * SI);
    float4 xa = __ldg(xp);
    float4 xb = __ldg(xp + 1);
    float x[8] = {xa.x, xa.y, xa.z, xa.w, xb.x, xb.y, xb.z, xb.w};

    float4 acc = make_float4(0.f, 0.f, 0.f, 0.f);
#pragma unroll
    for (int i = 0; i < SI; i++) {
        acc.x = fmaf(x[i], c.w[i].x, acc.x);
        acc.y = fmaf(x[i], c.w[i].y, acc.y);
        acc.z = fmaf(x[i], c.w[i].z, acc.z);
        acc.w = fmaf(x[i], c.w[i].w, acc.w);
    }

    acc.x *= nrm; acc.y *= nrm; acc.z *= nrm; acc.w *= nrm;
    red_add_v4(out + (size_t)d * OUT_FEAT + lane * 4, acc);
}

__global__ __launch_bounds__(256) void edge_kernel(
        const float* __restrict__ h,
        const float* __restrict__ weight,
        float* __restrict__ out,
        int nedges) {
    int gw   = (blockIdx.x * blockDim.x + threadIdx.x) >> 5;
    int lane = threadIdx.x & 31;
    int e0 = gw * EPW;
    if (e0 >= nedges) return;            // warp-uniform

    EdgeCtx c;
    c.b = lane >> 1;
    c.o0 = (lane & 1) * 4;
    c.t_cur = -1;

    if (e0 + EPW <= nedges) {
        int4 eds[EPW];
#pragma unroll
        for (int k = 0; k < EPW; k++) eds[k] = g_edges[e0 + k];  // MLP=8
#pragma unroll
        for (int k = 0; k < EPW; k++) process_edge(h, weight, out, c, eds[k], lane);
    } else {
        for (int e = e0; e < nedges; e++) {
            int4 ed = g_edges[e];
            process_edge(h, weight, out, c, ed, lane);
        }
    }
}

// ---------------------------------------------------------------------------
// Kernel C: in-place ReLU (float4 vectorized)
// ---------------------------------------------------------------------------
__global__ void relu_kernel(float4* __restrict__ out, int n4) {
    int i = blockIdx.x * blockDim.x + threadIdx.x;
    if (i >= n4) return;
    float4 v = out[i];
    v.x = fmaxf(v.x, 0.f);
    v.y = fmaxf(v.y, 0.f);
    v.z = fmaxf(v.z, 0.f);
    v.w = fmaxf(v.w, 0.f);
    out[i] = v;
}

// ---------------------------------------------------------------------------
// Launch: 3-kernel sort -> GEMM init -> edge scatter -> ReLU
// Inputs (metadata order): h, norm, weight, loop_weight, src, dst, etype
// ---------------------------------------------------------------------------
extern "C" void kernel_launch(void* const* d_in, const int* in_sizes, int n_in,
                              void* d_out, int out_size) {
    const float* h      = (const float*)d_in[0];
    const float* norm   = (const float*)d_in[1];
    const float* weight = (const float*)d_in[2];
    const float* lw     = (const float*)d_in[3];
    const int*   src    = (const int*)d_in[4];
    const int*   dst    = (const int*)d_in[5];
    const int*   etype  = (const int*)d_in[6];
    float* out = (float*)d_out;

    int nedges = in_sizes[4];
    if (nedges > E_MAX) nedges = E_MAX;
    int chunk = (nedges + NBLK2 - 1) / NBLK2;

    // ---- contention-free counting sort by etype (3 kernels) ----
    k_hist<<<NBLK2, SORT_TPB>>>(etype, nedges, chunk);
    k_scan<<<1, 256>>>();
    k_scatter<<<NBLK2, SORT_TPB>>>(src, dst, etype, norm, nedges, chunk);

    // ---- self-loop GEMM (initializes d_out) ----
    loop_gemm_kernel<<<(N_NODES + GM_ROWS - 1) / GM_ROWS, 256>>>(h, lw, out);

    // ---- per-edge messages (W cached in registers across EPW edges) ----
    {
        int nwarps = (nedges + EPW - 1) / EPW;
        int blocks = (nwarps + 7) / 8;       // 8 warps / block
        edge_kernel<<<blocks, 256>>>(h, weight, out, nedges);
    }

    // ---- ReLU ----
    {
        int n4 = N_NODES * OUT_FEAT / 4;
        relu_kernel<<<(n4 + 255) / 256, 256>>>((float4*)out, n4);
    }
}